// round 4
// baseline (speedup 1.0000x reference)
#include <cuda_runtime.h>

// ---------------- problem constants ----------------
#define IMGW   112
#define NPIX   12544          // 112*112
#define DIMC   256
#define QKC    256
#define QKVC   768            // q(256) + k(256) + v(256)
#define P2     49             // 7*7 windows
#define W2     256            // 16*16 pixels per window
#define HEADS  8
#define HD     32             // head dim (both q and v)
#define TOPK   4

// ---------------- scratch (static device memory; no allocs allowed) -------
__device__ float g_qkv [NPIX * QKVC];   // window layout: [(p*256+t)][768]
__device__ float g_qwin[P2 * QKC];
__device__ float g_kwin[P2 * QKC];
__device__ int   g_topidx[P2 * TOPK];
__device__ float g_attn[NPIX * DIMC];   // window layout
__device__ float g_z   [NPIX * DIMC];   // image layout

// window-row -> image-pixel index (row r = p*256 + t)
__device__ __forceinline__ int win_row_to_pixel(int r) {
    int p = r >> 8, t = r & 255;
    int wr = p / 7, wc = p - wr * 7;
    int i = t >> 4, j = t & 15;
    return (wr * 16 + i) * IMGW + (wc * 16 + j);
}

// ---------------- 128x128x8 SGEMM (optionally gathered A rows) ------------
// C[M,N] = A[M,K] @ B[K,N] + bias[N].  M,K multiples of 128/8; N mult of 128.
template<int GATHER>
__global__ __launch_bounds__(256)
void sgemm128_kernel(const float* __restrict__ A, const float* __restrict__ B,
                     const float* __restrict__ bias, float* __restrict__ C,
                     int N, int K)
{
    __shared__ float As[8][128];
    __shared__ float Bs[8][128];

    const int tid = threadIdx.x;
    const int tx  = tid & 15;      // 0..15  (col group)
    const int ty  = tid >> 4;      // 0..15  (row group)
    const int bm  = blockIdx.y;
    const int bn  = blockIdx.x;

    // A load: thread loads one float4 per k-step; row fixed for whole loop
    const int a_row_tile = tid >> 1;                 // 0..127
    const int a_c0       = (tid & 1) * 4;            // 0 or 4
    const int arow       = bm * 128 + a_row_tile;
    const int apix       = GATHER ? win_row_to_pixel(arow) : arow;
    const float* a_ptr   = A + (size_t)apix * K + a_c0;

    // B load: thread loads one float4 per k-step
    const int b_kr  = tid >> 5;                      // 0..7
    const int b_c0  = (tid & 31) * 4;                // 0..124
    const float* b_ptr = B + (size_t)b_kr * N + bn * 128 + b_c0;

    float acc[8][8];
    #pragma unroll
    for (int i = 0; i < 8; i++)
        #pragma unroll
        for (int j = 0; j < 8; j++) acc[i][j] = 0.f;

    for (int kb = 0; kb < K; kb += 8) {
        float4 av = *(const float4*)(a_ptr + kb);
        float4 bv = *(const float4*)(b_ptr + (size_t)kb * N);
        As[a_c0 + 0][a_row_tile] = av.x;
        As[a_c0 + 1][a_row_tile] = av.y;
        As[a_c0 + 2][a_row_tile] = av.z;
        As[a_c0 + 3][a_row_tile] = av.w;
        *(float4*)&Bs[b_kr][b_c0] = bv;
        __syncthreads();

        #pragma unroll
        for (int k = 0; k < 8; k++) {
            float af[8], bf[8];
            *(float4*)&af[0] = *(const float4*)&As[k][ty * 8];
            *(float4*)&af[4] = *(const float4*)&As[k][ty * 8 + 4];
            *(float4*)&bf[0] = *(const float4*)&Bs[k][tx * 8];
            *(float4*)&bf[4] = *(const float4*)&Bs[k][tx * 8 + 4];
            #pragma unroll
            for (int i = 0; i < 8; i++)
                #pragma unroll
                for (int j = 0; j < 8; j++)
                    acc[i][j] = fmaf(af[i], bf[j], acc[i][j]);
        }
        __syncthreads();
    }

    const int crow0 = bm * 128 + ty * 8;
    const int ccol0 = bn * 128 + tx * 8;
    float bvals[8];
    #pragma unroll
    for (int j = 0; j < 8; j++) bvals[j] = bias[ccol0 + j];
    #pragma unroll
    for (int i = 0; i < 8; i++) {
        float* crow = C + (size_t)(crow0 + i) * N + ccol0;
        float4 o0 = make_float4(acc[i][0] + bvals[0], acc[i][1] + bvals[1],
                                acc[i][2] + bvals[2], acc[i][3] + bvals[3]);
        float4 o1 = make_float4(acc[i][4] + bvals[4], acc[i][5] + bvals[5],
                                acc[i][6] + bvals[6], acc[i][7] + bvals[7]);
        *(float4*)(crow)     = o0;
        *(float4*)(crow + 4) = o1;
    }
}

// ---------------- per-window means of q and k -----------------------------
__global__ __launch_bounds__(256)
void means_kernel(const float* __restrict__ qkv,
                  float* __restrict__ qwin, float* __restrict__ kwin)
{
    int p = blockIdx.x, c = threadIdx.x;
    const float* base = qkv + (size_t)p * W2 * QKVC;
    float sq = 0.f, sk = 0.f;
    for (int t = 0; t < W2; t++) {
        sq += base[(size_t)t * QKVC + c];
        sk += base[(size_t)t * QKVC + QKC + c];
    }
    qwin[p * QKC + c] = sq * (1.f / 256.f);
    kwin[p * QKC + c] = sk * (1.f / 256.f);
}

// ---------------- routing: top-4 windows per window -----------------------
__global__ __launch_bounds__(64)
void route_kernel(const float* __restrict__ qwin, const float* __restrict__ kwin,
                  int* __restrict__ topidx)
{
    __shared__ float lg[P2];
    int p = blockIdx.x, j = threadIdx.x;
    if (j < P2) {
        float s = 0.f;
        const float* q = qwin + p * QKC;
        const float* k = kwin + j * QKC;
        for (int c = 0; c < QKC; c++) s += q[c] * k[c];
        lg[j] = s;                       // positive scale omitted: argmax-set invariant
    }
    __syncthreads();
    if (j == 0) {
        #pragma unroll
        for (int kk = 0; kk < TOPK; kk++) {
            float best = -1e30f; int bi = 0;
            for (int w = 0; w < P2; w++)
                if (lg[w] > best) { best = lg[w]; bi = w; }
            topidx[p * TOPK + kk] = bi;
            lg[bi] = -1e30f;
        }
    }
}

// ---------------- pixel attention (flash-style, per window x head) --------
__global__ __launch_bounds__(256)
void attn_kernel(const float* __restrict__ qkv, const int* __restrict__ topidx,
                 float* __restrict__ out)
{
    __shared__ float Ks[128 * 32];
    __shared__ float Vs[128 * 32];

    const int p = blockIdx.x, h = blockIdx.y, t = threadIdx.x;
    const float scale = 0.0625f;   // 256^-0.5

    // Q row in registers
    float4 qv[8];
    const float4* qsrc = (const float4*)(qkv + ((size_t)(p * W2 + t)) * QKVC + h * HD);
    #pragma unroll
    for (int i = 0; i < 8; i++) qv[i] = qsrc[i];

    float m = -1e30f, l = 0.f;
    float4 av[8];
    #pragma unroll
    for (int i = 0; i < 8; i++) av[i] = make_float4(0.f, 0.f, 0.f, 0.f);

    for (int cc = 0; cc < 2 * TOPK; cc++) {          // 8 chunks of 128 keys
        const int pw    = topidx[p * TOPK + (cc >> 1)];
        const int rbase = (cc & 1) * 128;
        __syncthreads();
        for (int li = t; li < 1024; li += 256) {     // 128 rows x 8 float4
            int row = li >> 3, c4 = li & 7;
            size_t off = ((size_t)(pw * W2 + rbase + row)) * QKVC + h * HD + c4 * 4;
            ((float4*)Ks)[li] = *(const float4*)(qkv + off + QKC);       // k
            ((float4*)Vs)[li] = *(const float4*)(qkv + off + 2 * QKC);   // v
        }
        __syncthreads();

        for (int j = 0; j < 128; j++) {
            const float4* kr = (const float4*)(Ks + j * 32);
            float s = 0.f;
            #pragma unroll
            for (int i = 0; i < 8; i++) {
                float4 k4 = kr[i];
                s = fmaf(qv[i].x, k4.x, s);
                s = fmaf(qv[i].y, k4.y, s);
                s = fmaf(qv[i].z, k4.z, s);
                s = fmaf(qv[i].w, k4.w, s);
            }
            s *= scale;
            const float4* vr = (const float4*)(Vs + j * 32);
            if (s > m) {
                float r = expf(m - s);
                m = s;
                l = l * r + 1.f;
                #pragma unroll
                for (int i = 0; i < 8; i++) {
                    float4 v4 = vr[i];
                    av[i].x = fmaf(av[i].x, r, v4.x);
                    av[i].y = fmaf(av[i].y, r, v4.y);
                    av[i].z = fmaf(av[i].z, r, v4.z);
                    av[i].w = fmaf(av[i].w, r, v4.w);
                }
            } else {
                float pe = expf(s - m);
                l += pe;
                #pragma unroll
                for (int i = 0; i < 8; i++) {
                    float4 v4 = vr[i];
                    av[i].x = fmaf(pe, v4.x, av[i].x);
                    av[i].y = fmaf(pe, v4.y, av[i].y);
                    av[i].z = fmaf(pe, v4.z, av[i].z);
                    av[i].w = fmaf(pe, v4.w, av[i].w);
                }
            }
        }
    }

    float inv = 1.f / l;
    float4* dst = (float4*)(out + ((size_t)(p * W2 + t)) * DIMC + h * HD);
    #pragma unroll
    for (int i = 0; i < 8; i++)
        dst[i] = make_float4(av[i].x * inv, av[i].y * inv, av[i].z * inv, av[i].w * inv);
}

// ---------------- LePE depthwise 3x3 + un-permute + add -------------------
__global__ __launch_bounds__(256)
void z_kernel(const float* __restrict__ qkv, const float* __restrict__ attn,
              const float* __restrict__ lw, const float* __restrict__ lb,
              float* __restrict__ Z)
{
    const int pix = blockIdx.x;
    const int c   = threadIdx.x;
    const int gh  = pix / IMGW, gw = pix - gh * IMGW;
    const int p   = (gh >> 4) * 7 + (gw >> 4);
    const int t   = ((gh & 15) << 4) + (gw & 15);

    float z = attn[((size_t)(p * W2 + t)) * DIMC + c] + lb[c];
    #pragma unroll
    for (int kh = 0; kh < 3; kh++) {
        #pragma unroll
        for (int kw = 0; kw < 3; kw++) {
            int hh = gh + kh - 1, ww = gw + kw - 1;
            if (hh >= 0 && hh < IMGW && ww >= 0 && ww < IMGW) {
                int pp = (hh >> 4) * 7 + (ww >> 4);
                int tt = ((hh & 15) << 4) + (ww & 15);
                float v = qkv[((size_t)(pp * W2 + tt)) * QKVC + 2 * QKC + c];
                z = fmaf(v, lw[(kh * 3 + kw) * DIMC + c], z);
            }
        }
    }
    Z[(size_t)pix * DIMC + c] = z;
}

// ---------------- launcher ------------------------------------------------
extern "C" void kernel_launch(void* const* d_in, const int* in_sizes, int n_in,
                              void* d_out, int out_size)
{
    const float* x      = (const float*)d_in[0];
    const float* w_qkv  = (const float*)d_in[1];
    const float* b_qkv  = (const float*)d_in[2];
    const float* w_o    = (const float*)d_in[3];
    const float* b_o    = (const float*)d_in[4];
    const float* lepe_w = (const float*)d_in[5];
    const float* lepe_b = (const float*)d_in[6];
    float* out = (float*)d_out;

    float *qkv, *qwin, *kwin, *attn, *z;
    int   *tidx;
    cudaGetSymbolAddress((void**)&qkv,  g_qkv);
    cudaGetSymbolAddress((void**)&qwin, g_qwin);
    cudaGetSymbolAddress((void**)&kwin, g_kwin);
    cudaGetSymbolAddress((void**)&tidx, g_topidx);
    cudaGetSymbolAddress((void**)&attn, g_attn);
    cudaGetSymbolAddress((void**)&z,    g_z);

    // 1) QKV projection (gathered rows -> window layout), M=12544 N=768 K=256
    sgemm128_kernel<1><<<dim3(768 / 128, NPIX / 128), 256>>>(x, w_qkv, b_qkv, qkv, 768, 256);
    // 2) window means
    means_kernel<<<P2, 256>>>(qkv, qwin, kwin);
    // 3) routing top-4
    route_kernel<<<P2, 64>>>(qwin, kwin, tidx);
    // 4) pixel attention
    attn_kernel<<<dim3(P2, HEADS), 256>>>(qkv, tidx, attn);
    // 5) LePE + un-permute + add
    z_kernel<<<NPIX, 256>>>(qkv, attn, lepe_w, lepe_b, z);
    // 6) output projection, M=12544 N=256 K=256 (image layout -> d_out)
    sgemm128_kernel<0><<<dim3(256 / 128, NPIX / 128), 256>>>(z, w_o, b_o, out, 256, 256);
}